// round 4
// baseline (speedup 1.0000x reference)
#include <cuda_runtime.h>

#define NTX 200000
#define NCL 100000
#define NME 20000
#define NEDGE 1000000
#define DD 64

// ---------------- static device scratch (no allocs allowed) ----------------
__device__ int d_deg0[NTX], d_deg1[NCL], d_deg2[NTX], d_deg3[NME];
__device__ int d_cur0[NTX], d_cur1[NCL], d_cur2[NTX], d_cur3[NME];
__device__ int d_row0[NTX + 1], d_row1[NCL + 1], d_row2[NTX + 1], d_row3[NME + 1];
__device__ int d_csr0[NEDGE], d_csr1[NEDGE], d_csr2[NEDGE], d_csr3[NEDGE];
__device__ float d_mean0[(size_t)NTX * DD];
__device__ float d_mean1[(size_t)NCL * DD];
__device__ float d_mean2[(size_t)NTX * DD];
__device__ float d_mean3[(size_t)NME * DD];
__device__ float d_htx[(size_t)NTX * DD];
__device__ float d_hcl[(size_t)NCL * DD];
__device__ float d_hme[(size_t)NME * DD];
__device__ int d_bsums[4 * 256];  // per-relation 256-entry regions
__device__ float d_wtx0[DD * DD], d_btx0[DD], d_wtx1[DD * DD], d_btx1[DD];

// per-relation helpers (device side)
__device__ __forceinline__ int rel_n(int rel) {
    return (rel == 0 || rel == 2) ? NTX : (rel == 1 ? NCL : NME);
}
__device__ __forceinline__ int *rel_deg(int rel) {
    return rel == 0 ? d_deg0 : rel == 1 ? d_deg1 : rel == 2 ? d_deg2 : d_deg3;
}
__device__ __forceinline__ int *rel_cur(int rel) {
    return rel == 0 ? d_cur0 : rel == 1 ? d_cur1 : rel == 2 ? d_cur2 : d_cur3;
}
__device__ __forceinline__ int *rel_row(int rel) {
    return rel == 0 ? d_row0 : rel == 1 ? d_row1 : rel == 2 ? d_row2 : d_row3;
}
__device__ __forceinline__ int *rel_csr(int rel) {
    return rel == 0 ? d_csr0 : rel == 1 ? d_csr1 : rel == 2 ? d_csr2 : d_csr3;
}

// ---------------- f32x2 helpers ----------------
__device__ __forceinline__ unsigned long long pk2(float a, float b) {
    unsigned long long r;
    asm("mov.b64 %0, {%1, %2};" : "=l"(r) : "f"(a), "f"(b));
    return r;
}
__device__ __forceinline__ void fma2(unsigned long long &d, unsigned long long a,
                                     unsigned long long b) {
    asm("fma.rn.f32x2 %0, %1, %2, %0;" : "+l"(d) : "l"(a), "l"(b));
}
__device__ __forceinline__ void upk2(unsigned long long v, float &x, float &y) {
    asm("mov.b64 {%0, %1}, %2;" : "=f"(x), "=f"(y) : "l"(v));
}

// ---------------- fused CSR build (blockIdx.y = relation) ----------------
__global__ void k_zero_counts() {
    int i = blockIdx.x * blockDim.x + threadIdx.x;
    if (i < NTX) { d_deg0[i] = 0; d_cur0[i] = 0; d_deg2[i] = 0; d_cur2[i] = 0; }
    if (i < NCL) { d_deg1[i] = 0; d_cur1[i] = 0; }
    if (i < NME) { d_deg3[i] = 0; d_cur3[i] = 0; }
}

__global__ void k_hist4(const int *__restrict__ dA, const int *__restrict__ dB,
                        const int *__restrict__ dC, const int *__restrict__ dD) {
    int rel = blockIdx.y;
    int i = blockIdx.x * blockDim.x + threadIdx.x;
    if (i >= NEDGE) return;
    const int *dst = rel == 0 ? dA : rel == 1 ? dB : rel == 2 ? dC : dD;
    atomicAdd(&rel_deg(rel)[dst[i]], 1);
}

__global__ void k_reduce4() {
    int rel = blockIdx.y;
    int n = rel_n(rel);
    const int *deg = rel_deg(rel);
    __shared__ int sm[1024];
    int t = threadIdx.x;
    int i = blockIdx.x * 1024 + t;
    sm[t] = (i < n) ? deg[i] : 0;
    __syncthreads();
    for (int s = 512; s > 0; s >>= 1) {
        if (t < s) sm[t] += sm[t + s];
        __syncthreads();
    }
    if (t == 0) d_bsums[rel * 256 + blockIdx.x] = sm[0];
}

__global__ void k_scan4() {  // 4 blocks x 256 threads: exclusive scan of each region
    int rel = blockIdx.x;
    __shared__ int s[256];
    int t = threadIdx.x;
    int v = d_bsums[rel * 256 + t];
    s[t] = v;
    __syncthreads();
    for (int off = 1; off < 256; off <<= 1) {
        int x = (t >= off) ? s[t - off] : 0;
        __syncthreads();
        if (t >= off) s[t] += x;
        __syncthreads();
    }
    d_bsums[rel * 256 + t] = s[t] - v;  // exclusive
}

__global__ void k_write4() {
    int rel = blockIdx.y;
    int n = rel_n(rel);
    const int *deg = rel_deg(rel);
    int *rowptr = rel_row(rel);
    __shared__ int s[1024];
    int t = threadIdx.x;
    int i = blockIdx.x * 1024 + t;
    int v = (i < n) ? deg[i] : 0;
    s[t] = v;
    __syncthreads();
    for (int off = 1; off < 1024; off <<= 1) {
        int x = (t >= off) ? s[t - off] : 0;
        __syncthreads();
        if (t >= off) s[t] += x;
        __syncthreads();
    }
    int incl = s[t];
    int base = d_bsums[rel * 256 + blockIdx.x];
    if (i < n) rowptr[i] = base + incl - v;
    if (i == n - 1) rowptr[n] = base + incl;
}

__global__ void k_fill4(const int *__restrict__ sA, const int *__restrict__ dA,
                        const int *__restrict__ sB, const int *__restrict__ dB,
                        const int *__restrict__ sC, const int *__restrict__ dC,
                        const int *__restrict__ sD, const int *__restrict__ dD) {
    int rel = blockIdx.y;
    int i = blockIdx.x * blockDim.x + threadIdx.x;
    if (i >= NEDGE) return;
    const int *src = rel == 0 ? sA : rel == 1 ? sB : rel == 2 ? sC : sD;
    const int *dst = rel == 0 ? dA : rel == 1 ? dB : rel == 2 ? dC : dD;
    int d = dst[i];
    int p = atomicAdd(&rel_cur(rel)[d], 1);
    rel_csr(rel)[rel_row(rel)[d] + p] = src[i];
}

// combined weight prep: wtx0 = Ws0[0]+Ws0[2], btx0 = b0[0]+b0[2], same for layer 1
__global__ void k_combine_all(const float *__restrict__ Ws0, const float *__restrict__ b0,
                              const float *__restrict__ Ws1, const float *__restrict__ b1) {
    int i = blockIdx.x * blockDim.x + threadIdx.x;
    if (i < 4096) {
        d_wtx0[i] = Ws0[i] + Ws0[2 * 4096 + i];
        d_wtx1[i] = Ws1[i] + Ws1[2 * 4096 + i];
    } else if (i < 4160) {
        int j = i - 4096;
        d_btx0[j] = b0[j] + b0[128 + j];
        d_btx1[j] = b1[j] + b1[128 + j];
    }
}

// -------- gather-side segment mean: HALF-warp per dst node, float4 lanes --------
__global__ void k_agg(const int *__restrict__ rowptr, const int *__restrict__ csr,
                      const float *__restrict__ hsrc, float *__restrict__ meanout, int n) {
    int hw = (blockIdx.x * blockDim.x + threadIdx.x) >> 4;  // global half-warp id
    int l = threadIdx.x & 15;
    if (hw >= n) return;
    int s0 = rowptr[hw], s1 = rowptr[hw + 1];
    float4 acc = make_float4(0.f, 0.f, 0.f, 0.f);
    const float4 *base = (const float4 *)hsrc;
    int e = s0;
    for (; e + 2 <= s1; e += 2) {
        int ia = __ldg(&csr[e]);
        int ib = __ldg(&csr[e + 1]);
        float4 va = __ldg(&base[(size_t)ia * 16 + l]);
        float4 vb = __ldg(&base[(size_t)ib * 16 + l]);
        acc.x += va.x + vb.x;
        acc.y += va.y + vb.y;
        acc.z += va.z + vb.z;
        acc.w += va.w + vb.w;
    }
    if (e < s1) {
        int ia = __ldg(&csr[e]);
        float4 va = __ldg(&base[(size_t)ia * 16 + l]);
        acc.x += va.x; acc.y += va.y; acc.z += va.z; acc.w += va.w;
    }
    int deg = s1 - s0;
    float inv = 1.f / (float)(deg > 0 ? deg : 1);
    ((float4 *)meanout)[(size_t)hw * 16 + l] =
        make_float4(acc.x * inv, acc.y * inv, acc.z * inv, acc.w * inv);
}

// ---------------- fused multi-input 64x64 GEMM with FFMA2 ----------------
// Stage 1: E[M,64] = act( sum_t Xt[M,64] @ Wt[64,64] + bias )   (act = leaky 0.01 if LEAKY)
// If FUSE_OUT: additionally Y2[M,64] = E @ Wout + bout  (E also written to Y)
template <int NIN, bool LEAKY, bool FUSE_OUT>
__global__ void __launch_bounds__(256, 2) k_gemm(
    const float *__restrict__ X0, const float *__restrict__ W0,
    const float *__restrict__ X1, const float *__restrict__ W1,
    const float *__restrict__ X2, const float *__restrict__ W2,
    const float *__restrict__ bias, float *__restrict__ Y, int M,
    const float *__restrict__ Wout, const float *__restrict__ bout,
    float *__restrict__ Y2) {
    extern __shared__ float smem[];
    constexpr int NW = NIN + (FUSE_OUT ? 1 : 0);
    float *sW = smem;                   // NW * 4096 (Wout last if fused)
    float *sA = smem + NW * 4096;       // 128 * 65 (padded)
    float *sB = sA + 128 * 65;          // 64 (+64 for bout if fused)
    const int tid = threadIdx.x;

#pragma unroll
    for (int t = 0; t < NIN; t++) {
        const float *W = (t == 0) ? W0 : ((t == 1) ? W1 : W2);
        const float4 *W4 = (const float4 *)W;
        float4 *sW4 = (float4 *)(sW + t * 4096);
        for (int i = tid; i < 1024; i += 256) sW4[i] = W4[i];
    }
    if (FUSE_OUT) {
        const float4 *W4 = (const float4 *)Wout;
        float4 *sW4 = (float4 *)(sW + NIN * 4096);
        for (int i = tid; i < 1024; i += 256) sW4[i] = W4[i];
        if (tid >= 64 && tid < 128) sB[tid] = bout[tid - 64];
    }
    if (tid < 64) sB[tid] = bias[tid];

    const int row0 = blockIdx.x * 128;
    const int ty = tid >> 3;  // 0..31 -> 4 rows each
    const int tx = tid & 7;   // 0..7  -> 8 cols each
    unsigned long long acc[4][4];
#pragma unroll
    for (int i = 0; i < 4; i++)
#pragma unroll
        for (int j = 0; j < 4; j++) acc[i][j] = 0ULL;

#pragma unroll
    for (int t = 0; t < NIN; t++) {
        const float *X = (t == 0) ? X0 : ((t == 1) ? X1 : X2);
        __syncthreads();  // protect sA reuse (also covers sW/sB writes on t==0)
        for (int u = tid; u < 2048; u += 256) {
            int r = u >> 4, c4 = u & 15;
            int gr = row0 + r;
            float4 v = make_float4(0.f, 0.f, 0.f, 0.f);
            if (gr < M) v = ((const float4 *)X)[(size_t)gr * 16 + c4];
            float *dp = &sA[r * 65 + c4 * 4];
            dp[0] = v.x; dp[1] = v.y; dp[2] = v.z; dp[3] = v.w;
        }
        __syncthreads();
        const float *wrow = sW + t * 4096 + tx * 8;
        const float *ap = &sA[(ty * 4) * 65];
#pragma unroll 8
        for (int k = 0; k < 64; k++) {
            unsigned long long a2[4];
#pragma unroll
            for (int i = 0; i < 4; i++) {
                float a = ap[i * 65 + k];
                a2[i] = pk2(a, a);
            }
            float4 w0 = *(const float4 *)(wrow + k * 64);
            float4 w1 = *(const float4 *)(wrow + k * 64 + 4);
            unsigned long long wb[4];
            wb[0] = pk2(w0.x, w0.y);
            wb[1] = pk2(w0.z, w0.w);
            wb[2] = pk2(w1.x, w1.y);
            wb[3] = pk2(w1.z, w1.w);
#pragma unroll
            for (int i = 0; i < 4; i++)
#pragma unroll
                for (int j = 0; j < 4; j++) fma2(acc[i][j], a2[i], wb[j]);
        }
    }

    // epilogue for stage 1: bias (+ optional activation), write E
    float eo[4][8];
#pragma unroll
    for (int i = 0; i < 4; i++) {
#pragma unroll
        for (int j = 0; j < 4; j++) upk2(acc[i][j], eo[i][2 * j], eo[i][2 * j + 1]);
#pragma unroll
        for (int c = 0; c < 8; c++) {
            float v = eo[i][c] + sB[tx * 8 + c];
            if (LEAKY) v = (v > 0.f) ? v : 0.01f * v;
            eo[i][c] = v;
        }
        int gr = row0 + ty * 4 + i;
        if (gr < M) {
            float4 *yp = (float4 *)(Y + (size_t)gr * 64 + tx * 8);
            yp[0] = make_float4(eo[i][0], eo[i][1], eo[i][2], eo[i][3]);
            yp[1] = make_float4(eo[i][4], eo[i][5], eo[i][6], eo[i][7]);
        }
    }

    if (FUSE_OUT) {
        // stash E tile into sA, then stage 2: Y2 = E @ Wout + bout
        __syncthreads();  // everyone done reading sA in stage 1
#pragma unroll
        for (int i = 0; i < 4; i++) {
            float *dp = &sA[(ty * 4 + i) * 65 + tx * 8];
#pragma unroll
            for (int c = 0; c < 8; c++) dp[c] = eo[i][c];
        }
        __syncthreads();
#pragma unroll
        for (int i = 0; i < 4; i++)
#pragma unroll
            for (int j = 0; j < 4; j++) acc[i][j] = 0ULL;
        const float *wrow = sW + NIN * 4096 + tx * 8;
        const float *ap = &sA[(ty * 4) * 65];
#pragma unroll 8
        for (int k = 0; k < 64; k++) {
            unsigned long long a2[4];
#pragma unroll
            for (int i = 0; i < 4; i++) {
                float a = ap[i * 65 + k];
                a2[i] = pk2(a, a);
            }
            float4 w0 = *(const float4 *)(wrow + k * 64);
            float4 w1 = *(const float4 *)(wrow + k * 64 + 4);
            unsigned long long wb[4];
            wb[0] = pk2(w0.x, w0.y);
            wb[1] = pk2(w0.z, w0.w);
            wb[2] = pk2(w1.x, w1.y);
            wb[3] = pk2(w1.z, w1.w);
#pragma unroll
            for (int i = 0; i < 4; i++)
#pragma unroll
                for (int j = 0; j < 4; j++) fma2(acc[i][j], a2[i], wb[j]);
        }
#pragma unroll
        for (int i = 0; i < 4; i++) {
            int gr = row0 + ty * 4 + i;
            if (gr >= M) continue;
            float o[8];
#pragma unroll
            for (int j = 0; j < 4; j++) upk2(acc[i][j], o[2 * j], o[2 * j + 1]);
#pragma unroll
            for (int c = 0; c < 8; c++) o[c] += sB[64 + tx * 8 + c];
            float4 *yp = (float4 *)(Y2 + (size_t)gr * 64 + tx * 8);
            yp[0] = make_float4(o[0], o[1], o[2], o[3]);
            yp[1] = make_float4(o[4], o[5], o[6], o[7]);
        }
    }
}

// ---------------- host ----------------
static inline void *symaddr(const void *s) {
    void *p = nullptr;
    cudaGetSymbolAddress(&p, s);
    return p;
}

extern "C" void kernel_launch(void *const *d_in, const int *in_sizes, int n_in,
                              void *d_out, int out_size) {
    const float *features = (const float *)d_in[0];
    const float *emb_client = (const float *)d_in[1];
    const float *emb_merchant = (const float *)d_in[2];
    const float *Ws0 = (const float *)d_in[3];
    const float *Wn0 = (const float *)d_in[4];
    const float *b0 = (const float *)d_in[5];
    const float *Ws1 = (const float *)d_in[6];
    const float *Wn1 = (const float *)d_in[7];
    const float *b1 = (const float *)d_in[8];
    const float *Wout = (const float *)d_in[9];
    const float *bout = (const float *)d_in[10];
    const int *e0s = (const int *)d_in[11], *e0d = (const int *)d_in[12];
    const int *e1s = (const int *)d_in[13], *e1d = (const int *)d_in[14];
    const int *e2s = (const int *)d_in[15], *e2d = (const int *)d_in[16];
    const int *e3s = (const int *)d_in[17], *e3d = (const int *)d_in[18];

    float *out = (float *)d_out;
    float *emb = out + (size_t)NTX * DD;  // tuple (out, embedding): embedding second

    int *row0 = (int *)symaddr(d_row0), *row1 = (int *)symaddr(d_row1);
    int *row2 = (int *)symaddr(d_row2), *row3 = (int *)symaddr(d_row3);
    int *csr0 = (int *)symaddr(d_csr0), *csr1 = (int *)symaddr(d_csr1);
    int *csr2 = (int *)symaddr(d_csr2), *csr3 = (int *)symaddr(d_csr3);
    float *mean0 = (float *)symaddr(d_mean0), *mean1 = (float *)symaddr(d_mean1);
    float *mean2 = (float *)symaddr(d_mean2), *mean3 = (float *)symaddr(d_mean3);
    float *htx = (float *)symaddr(d_htx), *hcl = (float *)symaddr(d_hcl);
    float *hme = (float *)symaddr(d_hme);
    float *wtx0 = (float *)symaddr(d_wtx0), *btx0 = (float *)symaddr(d_btx0);
    float *wtx1 = (float *)symaddr(d_wtx1), *btx1 = (float *)symaddr(d_btx1);

    const int SM3 = (3 * 4096 + 128 * 65 + 128) * 4;
    const int SM2 = (2 * 4096 + 128 * 65 + 128) * 4;
    const int SM4F = (4 * 4096 + 128 * 65 + 128) * 4;
    cudaFuncSetAttribute(k_gemm<3, true, false>, cudaFuncAttributeMaxDynamicSharedMemorySize, SM3);
    cudaFuncSetAttribute(k_gemm<2, true, false>, cudaFuncAttributeMaxDynamicSharedMemorySize, SM2);
    cudaFuncSetAttribute(k_gemm<3, false, true>, cudaFuncAttributeMaxDynamicSharedMemorySize, SM4F);

    // ---- fused CSR build: 6 launches total ----
    k_zero_counts<<<(NTX + 255) / 256, 256>>>();
    {
        dim3 ge((NEDGE + 255) / 256, 4);
        dim3 gn((NTX + 1023) / 1024, 4);  // max over relations; guarded inside
        k_hist4<<<ge, 256>>>(e0d, e1d, e2d, e3d);
        k_reduce4<<<gn, 1024>>>();
        k_scan4<<<4, 256>>>();
        k_write4<<<gn, 1024>>>();
        k_fill4<<<ge, 256>>>(e0s, e0d, e1s, e1d, e2s, e2d, e3s, e3d);
    }
    k_combine_all<<<(4160 + 255) / 256, 256>>>(Ws0, b0, Ws1, b1);

    // ---- layer 0 aggregation (all 4 relations); 16 half-warps per 256-thr block ----
    k_agg<<<(NTX + 15) / 16, 256>>>(row0, csr0, emb_client, mean0, NTX);
    k_agg<<<(NTX + 15) / 16, 256>>>(row2, csr2, emb_merchant, mean2, NTX);
    k_agg<<<(NCL + 15) / 16, 256>>>(row1, csr1, features, mean1, NCL);
    k_agg<<<(NME + 15) / 16, 256>>>(row3, csr3, features, mean3, NME);

    // ---- layer 0 GEMMs (+ leaky relu) ----
    k_gemm<3, true, false><<<(NTX + 127) / 128, 256, SM3>>>(
        features, wtx0, mean0, Wn0 + 0 * 4096, mean2, Wn0 + 2 * 4096, btx0, htx, NTX,
        nullptr, nullptr, nullptr);
    k_gemm<2, true, false><<<(NCL + 127) / 128, 256, SM2>>>(
        emb_client, Ws0 + 1 * 4096, mean1, Wn0 + 1 * 4096, nullptr, nullptr,
        b0 + 1 * 64, hcl, NCL, nullptr, nullptr, nullptr);
    k_gemm<2, true, false><<<(NME + 127) / 128, 256, SM2>>>(
        emb_merchant, Ws0 + 3 * 4096, mean3, Wn0 + 3 * 4096, nullptr, nullptr,
        b0 + 3 * 64, hme, NME, nullptr, nullptr, nullptr);

    // ---- layer 1 (tx only) + fused output head ----
    k_agg<<<(NTX + 15) / 16, 256>>>(row0, csr0, hcl, mean0, NTX);
    k_agg<<<(NTX + 15) / 16, 256>>>(row2, csr2, hme, mean2, NTX);
    k_gemm<3, false, true><<<(NTX + 127) / 128, 256, SM4F>>>(
        htx, wtx1, mean0, Wn1 + 0 * 4096, mean2, Wn1 + 2 * 4096, btx1, emb, NTX,
        Wout, bout, out);
}

// round 8
// speedup vs baseline: 1.0407x; 1.0407x over previous
#include <cuda_runtime.h>

#define NTX 200000
#define NCL 100000
#define NME 20000
#define NEDGE 1000000
#define DD 64

// ---------------- static device scratch (no allocs allowed) ----------------
__device__ int d_deg0[NTX], d_deg1[NCL], d_deg2[NTX], d_deg3[NME];
__device__ int d_cur0[NTX], d_cur1[NCL], d_cur2[NTX], d_cur3[NME];
__device__ int d_row0[NTX + 1], d_row1[NCL + 1], d_row2[NTX + 1], d_row3[NME + 1];
__device__ int d_csr0[NEDGE], d_csr1[NEDGE], d_csr2[NEDGE], d_csr3[NEDGE];
__device__ float d_mean0[(size_t)NTX * DD];
__device__ float d_mean1[(size_t)NCL * DD];
__device__ float d_mean2[(size_t)NTX * DD];
__device__ float d_mean3[(size_t)NME * DD];
__device__ float d_htx[(size_t)NTX * DD];
__device__ float d_hcl[(size_t)NCL * DD];
__device__ float d_hme[(size_t)NME * DD];
__device__ int d_bsums[4 * 256];  // per-relation 256-entry regions
__device__ float d_wtx0[DD * DD], d_btx0[DD], d_wtx1[DD * DD], d_btx1[DD];

// per-relation helpers (device side)
__device__ __forceinline__ int rel_n(int rel) {
    return (rel == 0 || rel == 2) ? NTX : (rel == 1 ? NCL : NME);
}
__device__ __forceinline__ int *rel_deg(int rel) {
    return rel == 0 ? d_deg0 : rel == 1 ? d_deg1 : rel == 2 ? d_deg2 : d_deg3;
}
__device__ __forceinline__ int *rel_cur(int rel) {
    return rel == 0 ? d_cur0 : rel == 1 ? d_cur1 : rel == 2 ? d_cur2 : d_cur3;
}
__device__ __forceinline__ int *rel_row(int rel) {
    return rel == 0 ? d_row0 : rel == 1 ? d_row1 : rel == 2 ? d_row2 : d_row3;
}
__device__ __forceinline__ int *rel_csr(int rel) {
    return rel == 0 ? d_csr0 : rel == 1 ? d_csr1 : rel == 2 ? d_csr2 : d_csr3;
}

// ---------------- f32x2 helpers ----------------
__device__ __forceinline__ unsigned long long pk2(float a, float b) {
    unsigned long long r;
    asm("mov.b64 %0, {%1, %2};" : "=l"(r) : "f"(a), "f"(b));
    return r;
}
__device__ __forceinline__ void fma2(unsigned long long &d, unsigned long long a,
                                     unsigned long long b) {
    asm("fma.rn.f32x2 %0, %1, %2, %0;" : "+l"(d) : "l"(a), "l"(b));
}
__device__ __forceinline__ void upk2(unsigned long long v, float &x, float &y) {
    asm("mov.b64 {%0, %1}, %2;" : "=f"(x), "=f"(y) : "l"(v));
}

// -------- preamble: zero counters AND combine tx self weights, one launch --------
__global__ void k_prep(const float *__restrict__ Ws0, const float *__restrict__ b0,
                       const float *__restrict__ Ws1, const float *__restrict__ b1) {
    int i = blockIdx.x * blockDim.x + threadIdx.x;
    if (i < NTX) { d_deg0[i] = 0; d_cur0[i] = 0; d_deg2[i] = 0; d_cur2[i] = 0; }
    if (i < NCL) { d_deg1[i] = 0; d_cur1[i] = 0; }
    if (i < NME) { d_deg3[i] = 0; d_cur3[i] = 0; }
    if (i < 4096) {
        d_wtx0[i] = Ws0[i] + Ws0[2 * 4096 + i];
        d_wtx1[i] = Ws1[i] + Ws1[2 * 4096 + i];
    } else if (i < 4160) {
        int j = i - 4096;
        d_btx0[j] = b0[j] + b0[128 + j];
        d_btx1[j] = b1[j] + b1[128 + j];
    }
}

// ---------------- fused CSR build (blockIdx.y = relation) ----------------
__global__ void k_hist4(const int *__restrict__ dA, const int *__restrict__ dB,
                        const int *__restrict__ dC, const int *__restrict__ dD) {
    int rel = blockIdx.y;
    int i = blockIdx.x * blockDim.x + threadIdx.x;
    if (i >= NEDGE) return;
    const int *dst = rel == 0 ? dA : rel == 1 ? dB : rel == 2 ? dC : dD;
    atomicAdd(&rel_deg(rel)[dst[i]], 1);
}

__global__ void k_reduce4() {
    int rel = blockIdx.y;
    int n = rel_n(rel);
    const int *deg = rel_deg(rel);
    __shared__ int sm[1024];
    int t = threadIdx.x;
    int i = blockIdx.x * 1024 + t;
    sm[t] = (i < n) ? deg[i] : 0;
    __syncthreads();
    for (int s = 512; s > 0; s >>= 1) {
        if (t < s) sm[t] += sm[t + s];
        __syncthreads();
    }
    if (t == 0) d_bsums[rel * 256 + blockIdx.x] = sm[0];
}

__global__ void k_scan4() {  // 4 blocks x 256 threads: exclusive scan of each region
    int rel = blockIdx.x;
    __shared__ int s[256];
    int t = threadIdx.x;
    int v = d_bsums[rel * 256 + t];
    s[t] = v;
    __syncthreads();
    for (int off = 1; off < 256; off <<= 1) {
        int x = (t >= off) ? s[t - off] : 0;
        __syncthreads();
        if (t >= off) s[t] += x;
        __syncthreads();
    }
    d_bsums[rel * 256 + t] = s[t] - v;  // exclusive
}

__global__ void k_write4() {
    int rel = blockIdx.y;
    int n = rel_n(rel);
    const int *deg = rel_deg(rel);
    int *rowptr = rel_row(rel);
    __shared__ int s[1024];
    int t = threadIdx.x;
    int i = blockIdx.x * 1024 + t;
    int v = (i < n) ? deg[i] : 0;
    s[t] = v;
    __syncthreads();
    for (int off = 1; off < 1024; off <<= 1) {
        int x = (t >= off) ? s[t - off] : 0;
        __syncthreads();
        if (t >= off) s[t] += x;
        __syncthreads();
    }
    int incl = s[t];
    int base = d_bsums[rel * 256 + blockIdx.x];
    if (i < n) rowptr[i] = base + incl - v;
    if (i == n - 1) rowptr[n] = base + incl;
}

__global__ void k_fill4(const int *__restrict__ sA, const int *__restrict__ dA,
                        const int *__restrict__ sB, const int *__restrict__ dB,
                        const int *__restrict__ sC, const int *__restrict__ dC,
                        const int *__restrict__ sD, const int *__restrict__ dD) {
    int rel = blockIdx.y;
    int i = blockIdx.x * blockDim.x + threadIdx.x;
    if (i >= NEDGE) return;
    const int *src = rel == 0 ? sA : rel == 1 ? sB : rel == 2 ? sC : sD;
    const int *dst = rel == 0 ? dA : rel == 1 ? dB : rel == 2 ? dC : dD;
    int d = dst[i];
    int p = atomicAdd(&rel_cur(rel)[d], 1);
    rel_csr(rel)[rel_row(rel)[d] + p] = src[i];
}

// -------- gather-side segment mean: HALF-warp per dst node, float4, MLP=4 --------
__device__ __forceinline__ void agg_one(const int *__restrict__ rowptr,
                                        const int *__restrict__ csr,
                                        const float *__restrict__ hsrc,
                                        float *__restrict__ meanout, int node, int l) {
    int s0 = rowptr[node], s1 = rowptr[node + 1];
    float4 acc = make_float4(0.f, 0.f, 0.f, 0.f);
    const float4 *base = (const float4 *)hsrc;
    int e = s0;
    for (; e + 4 <= s1; e += 4) {  // 4 independent LDG.128 chains in flight
        int ia = __ldg(&csr[e]);
        int ib = __ldg(&csr[e + 1]);
        int ic = __ldg(&csr[e + 2]);
        int id = __ldg(&csr[e + 3]);
        float4 va = __ldg(&base[(size_t)ia * 16 + l]);
        float4 vb = __ldg(&base[(size_t)ib * 16 + l]);
        float4 vc = __ldg(&base[(size_t)ic * 16 + l]);
        float4 vd = __ldg(&base[(size_t)id * 16 + l]);
        acc.x += (va.x + vb.x) + (vc.x + vd.x);
        acc.y += (va.y + vb.y) + (vc.y + vd.y);
        acc.z += (va.z + vb.z) + (vc.z + vd.z);
        acc.w += (va.w + vb.w) + (vc.w + vd.w);
    }
    for (; e < s1; e++) {
        int ia = __ldg(&csr[e]);
        float4 va = __ldg(&base[(size_t)ia * 16 + l]);
        acc.x += va.x; acc.y += va.y; acc.z += va.z; acc.w += va.w;
    }
    int deg = s1 - s0;
    float inv = 1.f / (float)(deg > 0 ? deg : 1);
    ((float4 *)meanout)[(size_t)node * 16 + l] =
        make_float4(acc.x * inv, acc.y * inv, acc.z * inv, acc.w * inv);
}

// layer-0: all 4 relations in one launch; hw index ranges pick the relation
#define L0_TOTAL (2 * NTX + NCL + NME)
__global__ void k_aggL0(const float *__restrict__ features,
                        const float *__restrict__ emb_client,
                        const float *__restrict__ emb_merchant) {
    int hw = (blockIdx.x * blockDim.x + threadIdx.x) >> 4;
    int l = threadIdx.x & 15;
    if (hw >= L0_TOTAL) return;
    if (hw < NTX) {
        agg_one(d_row0, d_csr0, emb_client, d_mean0, hw, l);
    } else if (hw < 2 * NTX) {
        agg_one(d_row2, d_csr2, emb_merchant, d_mean2, hw - NTX, l);
    } else if (hw < 2 * NTX + NCL) {
        agg_one(d_row1, d_csr1, features, d_mean1, hw - 2 * NTX, l);
    } else {
        agg_one(d_row3, d_csr3, features, d_mean3, hw - 2 * NTX - NCL, l);
    }
}

// layer-1: both tx-dst relations in one launch
__global__ void k_aggL1() {
    int hw = (blockIdx.x * blockDim.x + threadIdx.x) >> 4;
    int l = threadIdx.x & 15;
    if (hw >= 2 * NTX) return;
    if (hw < NTX) {
        agg_one(d_row0, d_csr0, d_hcl, d_mean0, hw, l);
    } else {
        agg_one(d_row2, d_csr2, d_hme, d_mean2, hw - NTX, l);
    }
}

// ---------------- fused multi-input 64x64 GEMM core with FFMA2 ----------------
// Stage 1: E[M,64] = act( sum_t Xt[M,64] @ Wt[64,64] + bias )   (act = leaky 0.01 if LEAKY)
// If FUSE_OUT: additionally Y2[M,64] = E @ Wout + bout  (E also written to Y)
template <int NIN, bool LEAKY, bool FUSE_OUT>
__device__ __forceinline__ void gemm_core(
    int row0,
    const float *__restrict__ X0, const float *__restrict__ W0,
    const float *__restrict__ X1, const float *__restrict__ W1,
    const float *__restrict__ X2, const float *__restrict__ W2,
    const float *__restrict__ bias, float *__restrict__ Y, int M,
    const float *__restrict__ Wout, const float *__restrict__ bout,
    float *__restrict__ Y2) {
    extern __shared__ float smem[];
    constexpr int NW = NIN + (FUSE_OUT ? 1 : 0);
    float *sW = smem;                   // NW * 4096 (Wout last if fused)
    float *sA = smem + NW * 4096;       // 128 * 65 (padded)
    float *sB = sA + 128 * 65;          // 64 (+64 for bout if fused)
    const int tid = threadIdx.x;

#pragma unroll
    for (int t = 0; t < NIN; t++) {
        const float *W = (t == 0) ? W0 : ((t == 1) ? W1 : W2);
        const float4 *W4 = (const float4 *)W;
        float4 *sW4 = (float4 *)(sW + t * 4096);
        for (int i = tid; i < 1024; i += 256) sW4[i] = W4[i];
    }
    if (FUSE_OUT) {
        const float4 *W4 = (const float4 *)Wout;
        float4 *sW4 = (float4 *)(sW + NIN * 4096);
        for (int i = tid; i < 1024; i += 256) sW4[i] = W4[i];
        if (tid >= 64 && tid < 128) sB[tid] = bout[tid - 64];
    }
    if (tid < 64) sB[tid] = bias[tid];

    const int ty = tid >> 3;  // 0..31 -> 4 rows each
    const int tx = tid & 7;   // 0..7  -> 8 cols each
    unsigned long long acc[4][4];
#pragma unroll
    for (int i = 0; i < 4; i++)
#pragma unroll
        for (int j = 0; j < 4; j++) acc[i][j] = 0ULL;

#pragma unroll
    for (int t = 0; t < NIN; t++) {
        const float *X = (t == 0) ? X0 : ((t == 1) ? X1 : X2);
        __syncthreads();  // protect sA reuse (also covers sW/sB writes on t==0)
        for (int u = tid; u < 2048; u += 256) {
            int r = u >> 4, c4 = u & 15;
            int gr = row0 + r;
            float4 v = make_float4(0.f, 0.f, 0.f, 0.f);
            if (gr < M) v = ((const float4 *)X)[(size_t)gr * 16 + c4];
            float *dp = &sA[r * 65 + c4 * 4];
            dp[0] = v.x; dp[1] = v.y; dp[2] = v.z; dp[3] = v.w;
        }
        __syncthreads();
        const float *wrow = sW + t * 4096 + tx * 8;
        const float *ap = &sA[(ty * 4) * 65];
#pragma unroll 8
        for (int k = 0; k < 64; k++) {
            unsigned long long a2[4];
#pragma unroll
            for (int i = 0; i < 4; i++) {
                float a = ap[i * 65 + k];
                a2[i] = pk2(a, a);
            }
            // LDS.128 directly into aligned register pairs: packed f32x2 operands, no MOVs
            ulonglong2 wp0 = *(const ulonglong2 *)(wrow + k * 64);
            ulonglong2 wp1 = *(const ulonglong2 *)(wrow + k * 64 + 4);
#pragma unroll
            for (int i = 0; i < 4; i++) {
                fma2(acc[i][0], a2[i], wp0.x);
                fma2(acc[i][1], a2[i], wp0.y);
                fma2(acc[i][2], a2[i], wp1.x);
                fma2(acc[i][3], a2[i], wp1.y);
            }
        }
    }

    // epilogue for stage 1: bias (+ optional activation), write E
    float eo[4][8];
#pragma unroll
    for (int i = 0; i < 4; i++) {
#pragma unroll
        for (int j = 0; j < 4; j++) upk2(acc[i][j], eo[i][2 * j], eo[i][2 * j + 1]);
#pragma unroll
        for (int c = 0; c < 8; c++) {
            float v = eo[i][c] + sB[tx * 8 + c];
            if (LEAKY) v = (v > 0.f) ? v : 0.01f * v;
            eo[i][c] = v;
        }
        int gr = row0 + ty * 4 + i;
        if (gr < M) {
            float4 *yp = (float4 *)(Y + (size_t)gr * 64 + tx * 8);
            yp[0] = make_float4(eo[i][0], eo[i][1], eo[i][2], eo[i][3]);
            yp[1] = make_float4(eo[i][4], eo[i][5], eo[i][6], eo[i][7]);
        }
    }

    if (FUSE_OUT) {
        // stash E tile into sA, then stage 2: Y2 = E @ Wout + bout
        __syncthreads();  // everyone done reading sA in stage 1
#pragma unroll
        for (int i = 0; i < 4; i++) {
            float *dp = &sA[(ty * 4 + i) * 65 + tx * 8];
#pragma unroll
            for (int c = 0; c < 8; c++) dp[c] = eo[i][c];
        }
        __syncthreads();
#pragma unroll
        for (int i = 0; i < 4; i++)
#pragma unroll
            for (int j = 0; j < 4; j++) acc[i][j] = 0ULL;
        const float *wrow = sW + NIN * 4096 + tx * 8;
        const float *ap = &sA[(ty * 4) * 65];
#pragma unroll 8
        for (int k = 0; k < 64; k++) {
            unsigned long long a2[4];
#pragma unroll
            for (int i = 0; i < 4; i++) {
                float a = ap[i * 65 + k];
                a2[i] = pk2(a, a);
            }
            ulonglong2 wp0 = *(const ulonglong2 *)(wrow + k * 64);
            ulonglong2 wp1 = *(const ulonglong2 *)(wrow + k * 64 + 4);
#pragma unroll
            for (int i = 0; i < 4; i++) {
                fma2(acc[i][0], a2[i], wp0.x);
                fma2(acc[i][1], a2[i], wp0.y);
                fma2(acc[i][2], a2[i], wp1.x);
                fma2(acc[i][3], a2[i], wp1.y);
            }
        }
#pragma unroll
        for (int i = 0; i < 4; i++) {
            int gr = row0 + ty * 4 + i;
            if (gr >= M) continue;
            float o[8];
#pragma unroll
            for (int j = 0; j < 4; j++) upk2(acc[i][j], o[2 * j], o[2 * j + 1]);
#pragma unroll
            for (int c = 0; c < 8; c++) o[c] += sB[64 + tx * 8 + c];
            float4 *yp = (float4 *)(Y2 + (size_t)gr * 64 + tx * 8);
            yp[0] = make_float4(o[0], o[1], o[2], o[3]);
            yp[1] = make_float4(o[4], o[5], o[6], o[7]);
        }
    }
}

// thin global wrappers
__global__ void __launch_bounds__(256, 2) k_gemm_tx0(
    const float *__restrict__ X0, const float *__restrict__ W1p,
    const float *__restrict__ W2p) {
    gemm_core<3, true, false>(blockIdx.x * 128, X0, d_wtx0, d_mean0, W1p, d_mean2, W2p,
                              d_btx0, d_htx, NTX, nullptr, nullptr, nullptr);
}

#define NBLK_CL ((NCL + 127) / 128)
#define NBLK_ME ((NME + 127) / 128)
__global__ void __launch_bounds__(256, 2) k_gemm_clme0(
    const float *__restrict__ emb_client, const float *__restrict__ emb_merchant,
    const float *__restrict__ Ws0, const float *__restrict__ Wn0,
    const float *__restrict__ b0) {
    if (blockIdx.x < NBLK_CL) {
        gemm_core<2, true, false>(blockIdx.x * 128, emb_client, Ws0 + 1 * 4096, d_mean1,
                                  Wn0 + 1 * 4096, nullptr, nullptr, b0 + 1 * 64, d_hcl,
                                  NCL, nullptr, nullptr, nullptr);
    } else {
        gemm_core<2, true, false>((blockIdx.x - NBLK_CL) * 128, emb_merchant,
                                  Ws0 + 3 * 4096, d_mean3, Wn0 + 3 * 4096, nullptr,
                                  nullptr, b0 + 3 * 64, d_hme, NME, nullptr, nullptr,
                                  nullptr);
    }
}

__global__ void __launch_bounds__(256, 2) k_gemm_tx1(
    const float *__restrict__ Wn1, const float *__restrict__ Wout,
    const float *__restrict__ bout, float *__restrict__ emb, float *__restrict__ out) {
    gemm_core<3, false, true>(blockIdx.x * 128, d_htx, d_wtx1, d_mean0, Wn1 + 0 * 4096,
                              d_mean2, Wn1 + 2 * 4096, d_btx1, emb, NTX, Wout, bout, out);
}

// ---------------- host ----------------
extern "C" void kernel_launch(void *const *d_in, const int *in_sizes, int n_in,
                              void *d_out, int out_size) {
    const float *features = (const float *)d_in[0];
    const float *emb_client = (const float *)d_in[1];
    const float *emb_merchant = (const float *)d_in[2];
    const float *Ws0 = (const float *)d_in[3];
    const float *Wn0 = (const float *)d_in[4];
    const float *b0 = (const float *)d_in[5];
    const float *Ws1 = (const float *)d_in[6];
    const float *Wn1 = (const float *)d_in[7];
    const float *b1 = (const float *)d_in[8];
    const float *Wout = (const float *)d_in[9];
    const float *bout = (const float *)d_in[10];
    const int *e0s = (const int *)d_in[11], *e0d = (const int *)d_in[12];
    const int *e1s = (const int *)d_in[13], *e1d = (const int *)d_in[14];
    const int *e2s = (const int *)d_in[15], *e2d = (const int *)d_in[16];
    const int *e3s = (const int *)d_in[17], *e3d = (const int *)d_in[18];

    float *out = (float *)d_out;
    float *emb = out + (size_t)NTX * DD;  // tuple (out, embedding): embedding second

    const int SM3 = (3 * 4096 + 128 * 65 + 128) * 4;
    const int SM2 = (2 * 4096 + 128 * 65 + 128) * 4;
    const int SM4F = (4 * 4096 + 128 * 65 + 128) * 4;
    cudaFuncSetAttribute(k_gemm_tx0, cudaFuncAttributeMaxDynamicSharedMemorySize, SM3);
    cudaFuncSetAttribute(k_gemm_clme0, cudaFuncAttributeMaxDynamicSharedMemorySize, SM2);
    cudaFuncSetAttribute(k_gemm_tx1, cudaFuncAttributeMaxDynamicSharedMemorySize, SM4F);

    // ---- preamble + fused CSR build: 6 launches ----
    k_prep<<<(NTX + 255) / 256, 256>>>(Ws0, b0, Ws1, b1);
    {
        dim3 ge((NEDGE + 255) / 256, 4);
        dim3 gn((NTX + 1023) / 1024, 4);  // max over relations; guarded inside
        k_hist4<<<ge, 256>>>(e0d, e1d, e2d, e3d);
        k_reduce4<<<gn, 1024>>>();
        k_scan4<<<4, 256>>>();
        k_write4<<<gn, 1024>>>();
        k_fill4<<<ge, 256>>>(e0s, e0d, e1s, e1d, e2s, e2d, e3s, e3d);
    }

    // ---- layer 0: one agg launch (all 4 relations), then GEMMs ----
    k_aggL0<<<(L0_TOTAL + 15) / 16, 256>>>(features, emb_client, emb_merchant);
    k_gemm_tx0<<<(NTX + 127) / 128, 256, SM3>>>(features, Wn0 + 0 * 4096,
                                                Wn0 + 2 * 4096);
    k_gemm_clme0<<<NBLK_CL + NBLK_ME, 256, SM2>>>(emb_client, emb_merchant, Ws0, Wn0, b0);

    // ---- layer 1 (tx only): one agg launch, then fused GEMM + output head ----
    k_aggL1<<<(2 * NTX + 15) / 16, 256>>>();
    k_gemm_tx1<<<(NTX + 127) / 128, 256, SM4F>>>(Wn1, Wout, bout, emb, out);
}